// round 16
// baseline (speedup 1.0000x reference)
#include <cuda_runtime.h>
#include <cstdint>

#define N_TOK 343
#define BATCH 256
#define HEADS 6
#define HDIM  32
#define CDIM  192
#define ODIM  576            // 3*C
#define MROWS 87808          // BATCH*N_TOK
#define NN2   117649         // 343*343
#define SCALE 0.17677669529663687f
#define LOG2E 1.4426950408889634f
#define QSCALE (SCALE * LOG2E)
#define NEGBIG (-1e30f)

// ---------------- scratch (device globals: no runtime allocation allowed) ----
// NOTE: only reference these from device code (host shadow trap — R5 bug).
__device__ float g_qkv[(size_t)MROWS * ODIM];      // [B*N, 3C]
__device__ float g_att[(size_t)MROWS * CDIM];      // [B*N, C]
// bias+mask in MMA-fragment tile order:
// [w][h][qt(3)*6+kt][wid(8)][nb(8)][lane(32)][4]  (8192 floats per 128x64 tile)
__device__ float g_bmt[(size_t)64 * HEADS * 18 * 8192];

// ---------------- common helpers -------------------------------------------
__device__ __forceinline__ float to_tf32(float x) {
    uint32_t u;
    asm("cvt.rna.tf32.f32 %0, %1;" : "=r"(u) : "f"(x));
    return __uint_as_float(u);
}

__device__ __forceinline__ void mma_tf32(float* d, const uint32_t* a, const uint32_t* b) {
    asm volatile(
        "mma.sync.aligned.m16n8k8.row.col.f32.tf32.tf32.f32 "
        "{%0,%1,%2,%3}, {%4,%5,%6,%7}, {%8,%9}, {%0,%1,%2,%3};\n"
        : "+f"(d[0]), "+f"(d[1]), "+f"(d[2]), "+f"(d[3])
        : "r"(a[0]), "r"(a[1]), "r"(a[2]), "r"(a[3]), "r"(b[0]), "r"(b[1]));
}

// ---------------- kernel 1: bias+mask -> fragment-tiled layout -------------
__global__ __launch_bounds__(256) void bm_precompute(
        const float* __restrict__ tab,
        const int* __restrict__ idx,
        const float* __restrict__ mask) {
    const int tile = blockIdx.x;        // qt*6 + kt
    const int h    = blockIdx.y;
    const int w    = blockIdx.z;
    const int qt   = tile / 6;
    const int kt   = tile % 6;
    const int t    = threadIdx.x;
    const int lane = t & 31;
    const int wid  = t >> 5;
    const int grp  = lane >> 2;
    const int tig  = lane & 3;

    const int qi0 = qt * 128 + wid * 16 + grp;
    const int qi1 = qi0 + 8;
    const float* mrow = mask + (size_t)w * NN2;

    float* dst = g_bmt + ((((size_t)w * HEADS + h) * 18 + tile) * 8 + wid) * 1024
               + lane * 4;

    #pragma unroll
    for (int nb = 0; nb < 8; nb++) {
        int kj0 = kt * 64 + nb * 8 + 2 * tig;
        int kj1 = kj0 + 1;
        float v[4];
        #pragma unroll
        for (int q = 0; q < 4; q++) {
            int qi = (q < 2) ? qi0 : qi1;
            int kj = (q & 1) ? kj1 : kj0;
            float r;
            if (qi >= N_TOK)      r = 0.f;
            else if (kj >= N_TOK) r = NEGBIG;
            else {
                int p = qi * N_TOK + kj;
                r = (tab[idx[p] * HEADS + h] + mrow[p]) * LOG2E;
            }
            v[q] = r;
        }
        *(float4*)(dst + nb * 128) = make_float4(v[0], v[1], v[2], v[3]);
    }
}

// ================= tensor-core GEMM via mma.sync (tf32) =====================
// CTA tile 256(M) x 64(N), K=192 in 4 chunks of 48. 8 warps 4(M)x2(N),
// warp tile 64x32 = 4x4 m16n8k8, 6 k-steps per chunk.
// No gmem reg-prefetch (frees 30 regs); instead the freed registers hold a
// DOUBLE-BUFFERED fragment set so the LDS for k-step s+1 overlaps the 16
// MMAs of k-step s (the R12 profile showed issue=19% from LDS->MMA stalls).
#define GK     192
#define GBK    48
#define NST    6
#define NCHK   4

// As: 16 mb x 6 s x 32 lanes x 4 = 12288 ; Bs: 8 nb x 6 s x 32 lanes x 2 = 3072
#define SM_GEMM_FLOATS (12288 + 3072)      // 61440 bytes

template <int DST>
__global__ __launch_bounds__(256, 2)
void gemm_tc(const float* __restrict__ Ain, const float* __restrict__ W,
             const float* __restrict__ bias, float* __restrict__ outp, int ocols) {
    const float* A   = (DST == 0) ? Ain : (const float*)g_att;
    float*       out = (DST == 0) ? (float*)g_qkv : outp;

    extern __shared__ float sm[];
    float* As = sm;            // 12288 floats
    float* Bs = sm + 12288;    // 3072 floats

    const int t    = threadIdx.x;
    const int lane = t & 31;
    const int wid  = t >> 5;
    const int o0   = blockIdx.x * 64;
    const int m0   = blockIdx.y * 256;
    const int wr   = wid >> 1;        // warp M index (0..3) -> 64 rows
    const int wc   = wid & 1;         // warp N index (0..1) -> 32 cols

    float acc[4][4][4];
    #pragma unroll
    for (int im = 0; im < 4; im++)
        #pragma unroll
        for (int jn = 0; jn < 4; jn++)
            #pragma unroll
            for (int q = 0; q < 4; q++) acc[im][jn][q] = 0.f;

    for (int chunk = 0; chunk < NCHK; chunk++) {
        const int k0 = chunk * GBK;
        __syncthreads();   // previous chunk's compute done before overwrite

        // ---- stage A [256 x 48] into fragment order (tf32) ----
        #pragma unroll
        for (int u = 0; u < 12; u++) {
            int e = u * 256 + t;          // 0..3071
            int r = e / 12;               // row 0..255
            int c = (e % 12) * 4;         // col 0..44
            float4 v = *(const float4*)(A + (size_t)(m0 + r) * GK + k0 + c);
            int grp = r & 7, hm = (r >> 3) & 1, mb = r >> 4;
            int s = c >> 3, hk = (c >> 2) & 1;
            int base = (((mb * NST + s) * 32) + grp * 4) * 4 + hm + 2 * hk;
            As[base + 0]  = to_tf32(v.x);
            As[base + 4]  = to_tf32(v.y);
            As[base + 8]  = to_tf32(v.z);
            As[base + 12] = to_tf32(v.w);
        }
        // ---- stage B [64 x 48] into fragment order (tf32) ----
        #pragma unroll
        for (int u = 0; u < 3; u++) {
            int e = u * 256 + t;          // 0..767
            int j = e / 12;               // n row 0..63
            int c = (e % 12) * 4;
            float4 v = *(const float4*)(W + (size_t)(o0 + j) * GK + k0 + c);
            int grp = j & 7, nb = j >> 3;
            int s = c >> 3, hk = (c >> 2) & 1;
            int base = (((nb * NST + s) * 32) + grp * 4) * 2 + hk;
            Bs[base + 0] = to_tf32(v.x);
            Bs[base + 2] = to_tf32(v.y);
            Bs[base + 4] = to_tf32(v.z);
            Bs[base + 6] = to_tf32(v.w);
        }
        __syncthreads();

        // ---- compute: 6 k-steps, fragment DOUBLE-BUFFERED across steps ----
        uint32_t a[2][4][4];
        uint32_t b[2][4][2];
        // preload s=0 into buffer 0
        #pragma unroll
        for (int im = 0; im < 4; im++) {
            const uint4 av = *(const uint4*)&As[(((wr * 4 + im) * NST + 0) * 32 + lane) * 4];
            a[0][im][0] = av.x; a[0][im][1] = av.y; a[0][im][2] = av.z; a[0][im][3] = av.w;
        }
        #pragma unroll
        for (int jn = 0; jn < 4; jn++) {
            const uint2 bv = *(const uint2*)&Bs[(((wc * 4 + jn) * NST + 0) * 32 + lane) * 2];
            b[0][jn][0] = bv.x; b[0][jn][1] = bv.y;
        }
        #pragma unroll
        for (int s = 0; s < NST; s++) {
            const int cur = s & 1, nxt = cur ^ 1;
            if (s + 1 < NST) {   // load next step's fragments before MMAs
                #pragma unroll
                for (int im = 0; im < 4; im++) {
                    const uint4 av = *(const uint4*)&As[(((wr * 4 + im) * NST + s + 1) * 32 + lane) * 4];
                    a[nxt][im][0] = av.x; a[nxt][im][1] = av.y;
                    a[nxt][im][2] = av.z; a[nxt][im][3] = av.w;
                }
                #pragma unroll
                for (int jn = 0; jn < 4; jn++) {
                    const uint2 bv = *(const uint2*)&Bs[(((wc * 4 + jn) * NST + s + 1) * 32 + lane) * 2];
                    b[nxt][jn][0] = bv.x; b[nxt][jn][1] = bv.y;
                }
            }
            #pragma unroll
            for (int im = 0; im < 4; im++)
                #pragma unroll
                for (int jn = 0; jn < 4; jn++)
                    mma_tf32(acc[im][jn], a[cur][im], b[cur][jn]);
        }
    }

    const int grp = lane >> 2;
    const int tig = lane & 3;
    #pragma unroll
    for (int im = 0; im < 4; im++) {
        #pragma unroll
        for (int jn = 0; jn < 4; jn++) {
            int col = o0 + wc * 32 + jn * 8 + tig * 2;
            float b0 = 0.f, b1 = 0.f;
            if (bias) { b0 = bias[col]; b1 = bias[col + 1]; }
            int row0 = m0 + wr * 64 + im * 16 + grp;
            float2 v0 = make_float2(acc[im][jn][0] + b0, acc[im][jn][1] + b1);
            float2 v1 = make_float2(acc[im][jn][2] + b0, acc[im][jn][3] + b1);
            *(float2*)(out + (size_t)row0 * ocols + col)       = v0;
            *(float2*)(out + (size_t)(row0 + 8) * ocols + col) = v1;
        }
    }
}

// ================= kernel 3: tensor-core flash attention ====================
// (unchanged from R12 — passing baseline)
#define ATT_SM_FLOATS (4096 + 2048 + 2048 + 8192)   // 16384 -> 65536 B

__global__ __launch_bounds__(256, 2) void attn_mma() {
    extern __shared__ float sm[];
    float* Qf = sm;                    // 4096
    float* Kf = sm + 4096;             // 2048
    float* Vf = sm + 6144;             // 2048
    float* Pf = sm + 8192;             // 8192

    const int t    = threadIdx.x;
    const int lane = t & 31;
    const int wid  = t >> 5;
    const int grp  = lane >> 2;
    const int tig  = lane & 3;

    const int qt = blockIdx.x;         // 0..2
    const int q0 = qt * 128;
    const int h  = blockIdx.y;
    const int b  = blockIdx.z;
    const int w  = b & 63;

    const float* qptr = g_qkv + (size_t)b * N_TOK * ODIM + h * HDIM;
    const float* kptr = qptr + CDIM;
    const float* vptr = qptr + 2 * CDIM;
    const float* bmtb = g_bmt + ((((size_t)w * HEADS + h) * 18 + qt * 6) * 8 + wid) * 1024
                      + lane * 4;

    // per-thread K/V staging geometry
    const int jj = t >> 2;             // key row 0..63
    const int db = (t & 3) * 8;        // d base

    // ---- prologue: prefetch K/V tile 0 ----
    float4 kva, kvb, kvc, kvd;
    {
        bool vld = jj < N_TOK;
        kva = kvb = kvc = kvd = make_float4(0.f, 0.f, 0.f, 0.f);
        if (vld) {
            kva = *(const float4*)(kptr + (size_t)jj * ODIM + db);
            kvb = *(const float4*)(kptr + (size_t)jj * ODIM + db + 4);
            kvc = *(const float4*)(vptr + (size_t)jj * ODIM + db);
            kvd = *(const float4*)(vptr + (size_t)jj * ODIM + db + 4);
        }
    }

    // ---- stage Q [128x32] into A-fragment order (tf32, pre-scaled), once ----
    {
        int r  = t >> 1;                 // 0..127
        int qi = q0 + r;
        int mb = r >> 4, g = r & 7, hm = (r >> 3) & 1;
        int dbq = (t & 1) * 16;
        #pragma unroll
        for (int c4 = 0; c4 < 4; c4++) {
            int d = dbq + c4 * 4;
            float4 v = make_float4(0.f, 0.f, 0.f, 0.f);
            if (qi < N_TOK) v = *(const float4*)(qptr + (size_t)qi * ODIM + d);
            int ks = d >> 3, hk = (d >> 2) & 1;
            float* dst = &Qf[mb * 512 + ks * 128 + g * 16 + hm + 2 * hk];
            dst[0]  = to_tf32(v.x * QSCALE);
            dst[4]  = to_tf32(v.y * QSCALE);
            dst[8]  = to_tf32(v.z * QSCALE);
            dst[12] = to_tf32(v.w * QSCALE);
        }
    }

    float mr[2], lr[2];
    mr[0] = NEGBIG; mr[1] = NEGBIG; lr[0] = 0.f; lr[1] = 0.f;
    float o[4][4];
    #pragma unroll
    for (int nb = 0; nb < 4; nb++)
        #pragma unroll
        for (int q = 0; q < 4; q++) o[nb][q] = 0.f;

    for (int kt = 0; kt < 6; kt++) {
        // ---- bias+mask fragments straight from gmem (consumed in softmax) ----
        float4 bmv[8];
        {
            const float* bt = bmtb + (size_t)kt * 8192;
            #pragma unroll
            for (int nb = 0; nb < 8; nb++)
                bmv[nb] = *(const float4*)(bt + nb * 128);
        }

        __syncthreads();   // prior tile's S/PV done reading Kf/Vf (+Q stage)

        // ---- STS K/V from prefetch regs ----
        {
            float* kd = &Kf[(jj >> 3) * 256 + (db >> 3) * 64 + (jj & 7) * 8];
            float4 w0 = make_float4(to_tf32(kva.x), to_tf32(kvb.x),
                                    to_tf32(kva.y), to_tf32(kvb.y));
            float4 w1 = make_float4(to_tf32(kva.z), to_tf32(kvb.z),
                                    to_tf32(kva.w), to_tf32(kvb.w));
            *(float4*)(kd + 0) = w0;
            *(float4*)(kd + 4) = w1;

            float* vd = &Vf[(jj >> 3) * 256 + (db >> 3) * 64 + ((jj & 7) & 3) * 2 + ((jj & 7) >> 2)];
            vd[0]  = to_tf32(kvc.x);
            vd[8]  = to_tf32(kvc.y);
            vd[16] = to_tf32(kvc.z);
            vd[24] = to_tf32(kvc.w);
            vd[32] = to_tf32(kvd.x);
            vd[40] = to_tf32(kvd.y);
            vd[48] = to_tf32(kvd.z);
            vd[56] = to_tf32(kvd.w);
        }

        // ---- prefetch K/V tile kt+1 into SAME regs (hides under compute) ----
        if (kt < 5) {
            int kj = (kt + 1) * 64 + jj;
            bool vld = kj < N_TOK;
            kva = kvb = kvc = kvd = make_float4(0.f, 0.f, 0.f, 0.f);
            if (vld) {
                kva = *(const float4*)(kptr + (size_t)kj * ODIM + db);
                kvb = *(const float4*)(kptr + (size_t)kj * ODIM + db + 4);
                kvc = *(const float4*)(vptr + (size_t)kj * ODIM + db);
                kvd = *(const float4*)(vptr + (size_t)kj * ODIM + db + 4);
            }
        }
        __syncthreads();

        // ---- S = Q K^T : warp tile 16x64 ----
        float s[8][4];
        #pragma unroll
        for (int nb = 0; nb < 8; nb++)
            #pragma unroll
            for (int q = 0; q < 4; q++) s[nb][q] = 0.f;

        #pragma unroll
        for (int ks = 0; ks < 4; ks++) {
            uint32_t a[4];
            const uint4 av = *(const uint4*)&Qf[wid * 512 + ks * 128 + lane * 4];
            a[0] = av.x; a[1] = av.y; a[2] = av.z; a[3] = av.w;
            #pragma unroll
            for (int nb = 0; nb < 8; nb++) {
                uint32_t bfr[2];
                const uint2 bv = *(const uint2*)&Kf[nb * 256 + ks * 64 + lane * 2];
                bfr[0] = bv.x; bfr[1] = bv.y;
                mma_tf32(s[nb], a, bfr);
            }
        }

        // ---- online softmax in exp2 domain (rows grp, grp+8) ----
        float rmax0 = NEGBIG, rmax1 = NEGBIG;
        #pragma unroll
        for (int nb = 0; nb < 8; nb++) {
            s[nb][0] += bmv[nb].x;
            s[nb][1] += bmv[nb].y;
            s[nb][2] += bmv[nb].z;
            s[nb][3] += bmv[nb].w;
            rmax0 = fmaxf(rmax0, fmaxf(s[nb][0], s[nb][1]));
            rmax1 = fmaxf(rmax1, fmaxf(s[nb][2], s[nb][3]));
        }
        rmax0 = fmaxf(rmax0, __shfl_xor_sync(0xffffffffu, rmax0, 1));
        rmax0 = fmaxf(rmax0, __shfl_xor_sync(0xffffffffu, rmax0, 2));
        rmax1 = fmaxf(rmax1, __shfl_xor_sync(0xffffffffu, rmax1, 1));
        rmax1 = fmaxf(rmax1, __shfl_xor_sync(0xffffffffu, rmax1, 2));

        float mn0 = fmaxf(mr[0], rmax0);
        float mn1 = fmaxf(mr[1], rmax1);
        float al0 = exp2f(mr[0] - mn0);
        float al1 = exp2f(mr[1] - mn1);
        mr[0] = mn0; mr[1] = mn1;

        float rs0 = 0.f, rs1 = 0.f;
        float* pw = Pf + wid * 1024 + grp * 16;
        const int off0 = ((2 * tig) & 3) * 4 + ((2 * tig) >> 2) * 2;
        const int off1 = ((2 * tig + 1) & 3) * 4 + ((2 * tig + 1) >> 2) * 2;
        #pragma unroll
        for (int nb = 0; nb < 8; nb++) {
            float p00 = exp2f(s[nb][0] - mn0);
            float p01 = exp2f(s[nb][1] - mn0);
            float p10 = exp2f(s[nb][2] - mn1);
            float p11 = exp2f(s[nb][3] - mn1);
            rs0 += p00 + p01;
            rs1 += p10 + p11;
            // S col-block nb == PV k-block; write P in PV A-fragment layout
            *(float2*)&pw[nb * 128 + off0] = make_float2(to_tf32(p00), to_tf32(p10));
            *(float2*)&pw[nb * 128 + off1] = make_float2(to_tf32(p01), to_tf32(p11));
        }
        rs0 += __shfl_xor_sync(0xffffffffu, rs0, 1);
        rs0 += __shfl_xor_sync(0xffffffffu, rs0, 2);
        rs1 += __shfl_xor_sync(0xffffffffu, rs1, 1);
        rs1 += __shfl_xor_sync(0xffffffffu, rs1, 2);
        lr[0] = lr[0] * al0 + rs0;
        lr[1] = lr[1] * al1 + rs1;

        // rescale O
        #pragma unroll
        for (int nb = 0; nb < 4; nb++) {
            o[nb][0] *= al0; o[nb][1] *= al0;
            o[nb][2] *= al1; o[nb][3] *= al1;
        }
        __syncwarp();   // Pf is per-warp: order STS before cross-lane LDS

        // ---- O += P V : 64 keys = 8 k-steps ----
        #pragma unroll
        for (int ks2 = 0; ks2 < 8; ks2++) {
            uint32_t a[4];
            const uint4 av = *(const uint4*)&Pf[wid * 1024 + ks2 * 128 + lane * 4];
            a[0] = av.x; a[1] = av.y; a[2] = av.z; a[3] = av.w;
            #pragma unroll
            for (int nb = 0; nb < 4; nb++) {
                uint32_t bfr[2];
                const uint2 bv = *(const uint2*)&Vf[ks2 * 256 + nb * 64 + lane * 2];
                bfr[0] = bv.x; bfr[1] = bv.y;
                mma_tf32(o[nb], a, bfr);
            }
        }
    }

    // ---- normalize + store [b, n, h*32+d] ----
    {
        float inv0 = 1.f / lr[0];
        float inv1 = 1.f / lr[1];
        int row0 = q0 + wid * 16 + grp;
        int row1 = row0 + 8;
        #pragma unroll
        for (int nb = 0; nb < 4; nb++) {
            int col = h * HDIM + nb * 8 + 2 * tig;
            if (row0 < N_TOK)
                *(float2*)&g_att[((size_t)b * N_TOK + row0) * CDIM + col] =
                    make_float2(o[nb][0] * inv0, o[nb][1] * inv0);
            if (row1 < N_TOK)
                *(float2*)&g_att[((size_t)b * N_TOK + row1) * CDIM + col] =
                    make_float2(o[nb][2] * inv1, o[nb][3] * inv1);
        }
    }
}

// ---------------- launch ----------------------------------------------------
extern "C" void kernel_launch(void* const* d_in, const int* in_sizes, int n_in,
                              void* d_out, int out_size) {
    (void)in_sizes; (void)n_in; (void)out_size;
    const float* x        = (const float*)d_in[0];
    const float* mask     = (const float*)d_in[1];
    const float* qkv_w    = (const float*)d_in[2];
    const float* proj_w   = (const float*)d_in[3];
    const float* proj_b   = (const float*)d_in[4];
    const float* bias_tab = (const float*)d_in[5];
    const int*   rel_idx  = (const int*)d_in[6];
    float* out = (float*)d_out;

    cudaFuncSetAttribute(attn_mma,
                         cudaFuncAttributeMaxDynamicSharedMemorySize,
                         ATT_SM_FLOATS * 4);
    cudaFuncSetAttribute(gemm_tc<0>,
                         cudaFuncAttributeMaxDynamicSharedMemorySize,
                         SM_GEMM_FLOATS * 4);
    cudaFuncSetAttribute(gemm_tc<1>,
                         cudaFuncAttributeMaxDynamicSharedMemorySize,
                         SM_GEMM_FLOATS * 4);

    bm_precompute<<<dim3(18, HEADS, 64), 256>>>(bias_tab, rel_idx, mask);
    gemm_tc<0><<<dim3(ODIM / 64, MROWS / 256), 256, SM_GEMM_FLOATS * 4>>>(
        x, qkv_w, nullptr, nullptr, ODIM);
    attn_mma<<<dim3(3, HEADS, BATCH), 256, ATT_SM_FLOATS * 4>>>();
    gemm_tc<1><<<dim3(CDIM / 64, MROWS / 256), 256, SM_GEMM_FLOATS * 4>>>(
        nullptr, proj_w, proj_b, out, CDIM);
}

// round 17
// speedup vs baseline: 1.1490x; 1.1490x over previous
#include <cuda_runtime.h>
#include <cstdint>

#define N_TOK 343
#define BATCH 256
#define HEADS 6
#define HDIM  32
#define CDIM  192
#define ODIM  576            // 3*C
#define MROWS 87808          // BATCH*N_TOK
#define NN2   117649         // 343*343
#define SCALE 0.17677669529663687f
#define LOG2E 1.4426950408889634f
#define QSCALE (SCALE * LOG2E)
#define NEGBIG (-1e30f)

// ---------------- scratch (device globals: no runtime allocation allowed) ----
// NOTE: only reference these from device code (host shadow trap — R5 bug).
__device__ float g_qkv[(size_t)MROWS * ODIM];      // [B*N, 3C]
__device__ float g_att[(size_t)MROWS * CDIM];      // [B*N, C]
// bias+mask in MMA-fragment tile order:
// [w][h][qt(3)*6+kt][wid(8)][nb(8)][lane(32)][4]  (8192 floats per 128x64 tile)
__device__ float g_bmt[(size_t)64 * HEADS * 18 * 8192];

// ---------------- common helpers -------------------------------------------
__device__ __forceinline__ float to_tf32(float x) {
    uint32_t u;
    asm("cvt.rna.tf32.f32 %0, %1;" : "=r"(u) : "f"(x));
    return __uint_as_float(u);
}

__device__ __forceinline__ void mma_tf32(float* d, const uint32_t* a, const uint32_t* b) {
    asm volatile(
        "mma.sync.aligned.m16n8k8.row.col.f32.tf32.tf32.f32 "
        "{%0,%1,%2,%3}, {%4,%5,%6,%7}, {%8,%9}, {%0,%1,%2,%3};\n"
        : "+f"(d[0]), "+f"(d[1]), "+f"(d[2]), "+f"(d[3])
        : "r"(a[0]), "r"(a[1]), "r"(a[2]), "r"(a[3]), "r"(b[0]), "r"(b[1]));
}

// ---------------- kernel 1: bias+mask -> fragment-tiled layout -------------
__global__ __launch_bounds__(256) void bm_precompute(
        const float* __restrict__ tab,
        const int* __restrict__ idx,
        const float* __restrict__ mask) {
    const int tile = blockIdx.x;        // qt*6 + kt
    const int h    = blockIdx.y;
    const int w    = blockIdx.z;
    const int qt   = tile / 6;
    const int kt   = tile % 6;
    const int t    = threadIdx.x;
    const int lane = t & 31;
    const int wid  = t >> 5;
    const int grp  = lane >> 2;
    const int tig  = lane & 3;

    const int qi0 = qt * 128 + wid * 16 + grp;
    const int qi1 = qi0 + 8;
    const float* mrow = mask + (size_t)w * NN2;

    float* dst = g_bmt + ((((size_t)w * HEADS + h) * 18 + tile) * 8 + wid) * 1024
               + lane * 4;

    #pragma unroll
    for (int nb = 0; nb < 8; nb++) {
        int kj0 = kt * 64 + nb * 8 + 2 * tig;
        int kj1 = kj0 + 1;
        float v[4];
        #pragma unroll
        for (int q = 0; q < 4; q++) {
            int qi = (q < 2) ? qi0 : qi1;
            int kj = (q & 1) ? kj1 : kj0;
            float r;
            if (qi >= N_TOK)      r = 0.f;
            else if (kj >= N_TOK) r = NEGBIG;
            else {
                int p = qi * N_TOK + kj;
                r = (tab[idx[p] * HEADS + h] + mrow[p]) * LOG2E;
            }
            v[q] = r;
        }
        *(float4*)(dst + nb * 128) = make_float4(v[0], v[1], v[2], v[3]);
    }
}

// ================= tensor-core GEMM via mma.sync (tf32) =====================
// CTA tile 128(M) x 192(N), K=192 in 4 chunks of 48. 8 warps 2(M)x4(N),
// warp tile 64x48 = 4x6 m16n8k8, 6 k-steps per chunk. occ 1 (96 acc regs);
// gmem reg-prefetch pipeline (regs free at occ 1) hides LDG under MMA.
// Rationale (R16 post-mortem): kernel is L1-traffic bound; this tile cuts
// l1tex bytes/FLOP by ~1.36x and A gmem re-reads by 3x vs 256x64.
#define GK     192
#define GBK    48
#define NST    6
#define NCHK   4

// As: 8 mb x 6 s x 32 lanes x 4 = 6144 ; Bs: 24 nb x 6 s x 32 lanes x 2 = 9216
#define SM_GEMM_FLOATS (6144 + 9216)       // 61440 bytes

template <int DST>
__global__ __launch_bounds__(256, 1)
void gemm_tc(const float* __restrict__ Ain, const float* __restrict__ W,
             const float* __restrict__ bias, float* __restrict__ outp, int ocols) {
    const float* A   = (DST == 0) ? Ain : (const float*)g_att;
    float*       out = (DST == 0) ? (float*)g_qkv : outp;

    extern __shared__ float sm[];
    float* As = sm;            // 6144 floats
    float* Bs = sm + 6144;     // 9216 floats

    const int t    = threadIdx.x;
    const int lane = t & 31;
    const int wid  = t >> 5;
    const int o0   = blockIdx.x * 192;
    const int m0   = blockIdx.y * 128;
    const int wr   = wid >> 2;        // warp M index (0..1) -> 64 rows
    const int wcn  = wid & 3;         // warp N index (0..3) -> 48 cols

    float acc[4][6][4];
    #pragma unroll
    for (int im = 0; im < 4; im++)
        #pragma unroll
        for (int jn = 0; jn < 6; jn++)
            #pragma unroll
            for (int q = 0; q < 4; q++) acc[im][jn][q] = 0.f;

    float4 pa[6];      // A chunk: 128x48 = 1536 float4 / 256 thr
    float4 pb[9];      // B chunk: 192x48 = 2304 float4 / 256 thr

    // ---- prologue: prefetch chunk 0 ----
    #pragma unroll
    for (int u = 0; u < 6; u++) {
        int e = u * 256 + t;
        int r = e / 12;
        int c = (e % 12) * 4;
        pa[u] = *(const float4*)(A + (size_t)(m0 + r) * GK + c);
    }
    #pragma unroll
    for (int u = 0; u < 9; u++) {
        int e = u * 256 + t;
        int j = e / 12;
        int c = (e % 12) * 4;
        pb[u] = *(const float4*)(W + (size_t)(o0 + j) * GK + c);
    }

    for (int chunk = 0; chunk < NCHK; chunk++) {
        __syncthreads();   // prior compute done reading fragment smem

        // ---- cvt + STS from prefetch regs ----
        #pragma unroll
        for (int u = 0; u < 6; u++) {
            int e = u * 256 + t;
            int r = e / 12;
            int c = (e % 12) * 4;
            int grp = r & 7, hm = (r >> 3) & 1, mb = r >> 4;
            int s = c >> 3, hk = (c >> 2) & 1;
            int base = (((mb * NST + s) * 32) + grp * 4) * 4 + hm + 2 * hk;
            As[base + 0]  = to_tf32(pa[u].x);
            As[base + 4]  = to_tf32(pa[u].y);
            As[base + 8]  = to_tf32(pa[u].z);
            As[base + 12] = to_tf32(pa[u].w);
        }
        #pragma unroll
        for (int u = 0; u < 9; u++) {
            int e = u * 256 + t;
            int j = e / 12;
            int c = (e % 12) * 4;
            int grp = j & 7, nb = j >> 3;
            int s = c >> 3, hk = (c >> 2) & 1;
            int base = (((nb * NST + s) * 32) + grp * 4) * 2 + hk;
            Bs[base + 0] = to_tf32(pb[u].x);
            Bs[base + 2] = to_tf32(pb[u].y);
            Bs[base + 4] = to_tf32(pb[u].z);
            Bs[base + 6] = to_tf32(pb[u].w);
        }

        // ---- prefetch next chunk into SAME regs (WAR after STS) ----
        if (chunk < NCHK - 1) {
            const int k0n = (chunk + 1) * GBK;
            #pragma unroll
            for (int u = 0; u < 6; u++) {
                int e = u * 256 + t;
                int r = e / 12;
                int c = (e % 12) * 4;
                pa[u] = *(const float4*)(A + (size_t)(m0 + r) * GK + k0n + c);
            }
            #pragma unroll
            for (int u = 0; u < 9; u++) {
                int e = u * 256 + t;
                int j = e / 12;
                int c = (e % 12) * 4;
                pb[u] = *(const float4*)(W + (size_t)(o0 + j) * GK + k0n + c);
            }
        }
        __syncthreads();

        // ---- compute: 6 k-steps of 4x6 m16n8k8 ----
        #pragma unroll
        for (int s = 0; s < NST; s++) {
            uint32_t a[4][4];
            #pragma unroll
            for (int im = 0; im < 4; im++) {
                const uint4 av = *(const uint4*)&As[(((wr * 4 + im) * NST + s) * 32 + lane) * 4];
                a[im][0] = av.x; a[im][1] = av.y; a[im][2] = av.z; a[im][3] = av.w;
            }
            uint32_t b[6][2];
            #pragma unroll
            for (int jn = 0; jn < 6; jn++) {
                const uint2 bv = *(const uint2*)&Bs[(((wcn * 6 + jn) * NST + s) * 32 + lane) * 2];
                b[jn][0] = bv.x; b[jn][1] = bv.y;
            }
            #pragma unroll
            for (int im = 0; im < 4; im++)
                #pragma unroll
                for (int jn = 0; jn < 6; jn++)
                    mma_tf32(acc[im][jn], a[im], b[jn]);
        }
    }

    const int grp = lane >> 2;
    const int tig = lane & 3;
    #pragma unroll
    for (int im = 0; im < 4; im++) {
        #pragma unroll
        for (int jn = 0; jn < 6; jn++) {
            int col = o0 + wcn * 48 + jn * 8 + tig * 2;
            float b0 = 0.f, b1 = 0.f;
            if (bias) { b0 = bias[col]; b1 = bias[col + 1]; }
            int row0 = m0 + wr * 64 + im * 16 + grp;
            float2 v0 = make_float2(acc[im][jn][0] + b0, acc[im][jn][1] + b1);
            float2 v1 = make_float2(acc[im][jn][2] + b0, acc[im][jn][3] + b1);
            *(float2*)(out + (size_t)row0 * ocols + col)       = v0;
            *(float2*)(out + (size_t)(row0 + 8) * ocols + col) = v1;
        }
    }
}

// ================= kernel 3: tensor-core flash attention ====================
// (unchanged from R12 — the 884us baseline)
#define ATT_SM_FLOATS (4096 + 2048 + 2048 + 8192)   // 16384 -> 65536 B

__global__ __launch_bounds__(256, 2) void attn_mma() {
    extern __shared__ float sm[];
    float* Qf = sm;                    // 4096
    float* Kf = sm + 4096;             // 2048
    float* Vf = sm + 6144;             // 2048
    float* Pf = sm + 8192;             // 8192

    const int t    = threadIdx.x;
    const int lane = t & 31;
    const int wid  = t >> 5;
    const int grp  = lane >> 2;
    const int tig  = lane & 3;

    const int qt = blockIdx.x;         // 0..2
    const int q0 = qt * 128;
    const int h  = blockIdx.y;
    const int b  = blockIdx.z;
    const int w  = b & 63;

    const float* qptr = g_qkv + (size_t)b * N_TOK * ODIM + h * HDIM;
    const float* kptr = qptr + CDIM;
    const float* vptr = qptr + 2 * CDIM;
    const float* bmtb = g_bmt + ((((size_t)w * HEADS + h) * 18 + qt * 6) * 8 + wid) * 1024
                      + lane * 4;

    // per-thread K/V staging geometry
    const int jj = t >> 2;             // key row 0..63
    const int db = (t & 3) * 8;        // d base

    // ---- prologue: prefetch K/V tile 0 ----
    float4 kva, kvb, kvc, kvd;
    {
        bool vld = jj < N_TOK;
        kva = kvb = kvc = kvd = make_float4(0.f, 0.f, 0.f, 0.f);
        if (vld) {
            kva = *(const float4*)(kptr + (size_t)jj * ODIM + db);
            kvb = *(const float4*)(kptr + (size_t)jj * ODIM + db + 4);
            kvc = *(const float4*)(vptr + (size_t)jj * ODIM + db);
            kvd = *(const float4*)(vptr + (size_t)jj * ODIM + db + 4);
        }
    }

    // ---- stage Q [128x32] into A-fragment order (tf32, pre-scaled), once ----
    {
        int r  = t >> 1;                 // 0..127
        int qi = q0 + r;
        int mb = r >> 4, g = r & 7, hm = (r >> 3) & 1;
        int dbq = (t & 1) * 16;
        #pragma unroll
        for (int c4 = 0; c4 < 4; c4++) {
            int d = dbq + c4 * 4;
            float4 v = make_float4(0.f, 0.f, 0.f, 0.f);
            if (qi < N_TOK) v = *(const float4*)(qptr + (size_t)qi * ODIM + d);
            int ks = d >> 3, hk = (d >> 2) & 1;
            float* dst = &Qf[mb * 512 + ks * 128 + g * 16 + hm + 2 * hk];
            dst[0]  = to_tf32(v.x * QSCALE);
            dst[4]  = to_tf32(v.y * QSCALE);
            dst[8]  = to_tf32(v.z * QSCALE);
            dst[12] = to_tf32(v.w * QSCALE);
        }
    }

    float mr[2], lr[2];
    mr[0] = NEGBIG; mr[1] = NEGBIG; lr[0] = 0.f; lr[1] = 0.f;
    float o[4][4];
    #pragma unroll
    for (int nb = 0; nb < 4; nb++)
        #pragma unroll
        for (int q = 0; q < 4; q++) o[nb][q] = 0.f;

    for (int kt = 0; kt < 6; kt++) {
        // ---- bias+mask fragments straight from gmem (consumed in softmax) ----
        float4 bmv[8];
        {
            const float* bt = bmtb + (size_t)kt * 8192;
            #pragma unroll
            for (int nb = 0; nb < 8; nb++)
                bmv[nb] = *(const float4*)(bt + nb * 128);
        }

        __syncthreads();   // prior tile's S/PV done reading Kf/Vf (+Q stage)

        // ---- STS K/V from prefetch regs ----
        {
            float* kd = &Kf[(jj >> 3) * 256 + (db >> 3) * 64 + (jj & 7) * 8];
            float4 w0 = make_float4(to_tf32(kva.x), to_tf32(kvb.x),
                                    to_tf32(kva.y), to_tf32(kvb.y));
            float4 w1 = make_float4(to_tf32(kva.z), to_tf32(kvb.z),
                                    to_tf32(kva.w), to_tf32(kvb.w));
            *(float4*)(kd + 0) = w0;
            *(float4*)(kd + 4) = w1;

            float* vd = &Vf[(jj >> 3) * 256 + (db >> 3) * 64 + ((jj & 7) & 3) * 2 + ((jj & 7) >> 2)];
            vd[0]  = to_tf32(kvc.x);
            vd[8]  = to_tf32(kvc.y);
            vd[16] = to_tf32(kvc.z);
            vd[24] = to_tf32(kvc.w);
            vd[32] = to_tf32(kvd.x);
            vd[40] = to_tf32(kvd.y);
            vd[48] = to_tf32(kvd.z);
            vd[56] = to_tf32(kvd.w);
        }

        // ---- prefetch K/V tile kt+1 into SAME regs (hides under compute) ----
        if (kt < 5) {
            int kj = (kt + 1) * 64 + jj;
            bool vld = kj < N_TOK;
            kva = kvb = kvc = kvd = make_float4(0.f, 0.f, 0.f, 0.f);
            if (vld) {
                kva = *(const float4*)(kptr + (size_t)kj * ODIM + db);
                kvb = *(const float4*)(kptr + (size_t)kj * ODIM + db + 4);
                kvc = *(const float4*)(vptr + (size_t)kj * ODIM + db);
                kvd = *(const float4*)(vptr + (size_t)kj * ODIM + db + 4);
            }
        }
        __syncthreads();

        // ---- S = Q K^T : warp tile 16x64 ----
        float s[8][4];
        #pragma unroll
        for (int nb = 0; nb < 8; nb++)
            #pragma unroll
            for (int q = 0; q < 4; q++) s[nb][q] = 0.f;

        #pragma unroll
        for (int ks = 0; ks < 4; ks++) {
            uint32_t a[4];
            const uint4 av = *(const uint4*)&Qf[wid * 512 + ks * 128 + lane * 4];
            a[0] = av.x; a[1] = av.y; a[2] = av.z; a[3] = av.w;
            #pragma unroll
            for (int nb = 0; nb < 8; nb++) {
                uint32_t bfr[2];
                const uint2 bv = *(const uint2*)&Kf[nb * 256 + ks * 64 + lane * 2];
                bfr[0] = bv.x; bfr[1] = bv.y;
                mma_tf32(s[nb], a, bfr);
            }
        }

        // ---- online softmax in exp2 domain (rows grp, grp+8) ----
        float rmax0 = NEGBIG, rmax1 = NEGBIG;
        #pragma unroll
        for (int nb = 0; nb < 8; nb++) {
            s[nb][0] += bmv[nb].x;
            s[nb][1] += bmv[nb].y;
            s[nb][2] += bmv[nb].z;
            s[nb][3] += bmv[nb].w;
            rmax0 = fmaxf(rmax0, fmaxf(s[nb][0], s[nb][1]));
            rmax1 = fmaxf(rmax1, fmaxf(s[nb][2], s[nb][3]));
        }
        rmax0 = fmaxf(rmax0, __shfl_xor_sync(0xffffffffu, rmax0, 1));
        rmax0 = fmaxf(rmax0, __shfl_xor_sync(0xffffffffu, rmax0, 2));
        rmax1 = fmaxf(rmax1, __shfl_xor_sync(0xffffffffu, rmax1, 1));
        rmax1 = fmaxf(rmax1, __shfl_xor_sync(0xffffffffu, rmax1, 2));

        float mn0 = fmaxf(mr[0], rmax0);
        float mn1 = fmaxf(mr[1], rmax1);
        float al0 = exp2f(mr[0] - mn0);
        float al1 = exp2f(mr[1] - mn1);
        mr[0] = mn0; mr[1] = mn1;

        float rs0 = 0.f, rs1 = 0.f;
        float* pw = Pf + wid * 1024 + grp * 16;
        const int off0 = ((2 * tig) & 3) * 4 + ((2 * tig) >> 2) * 2;
        const int off1 = ((2 * tig + 1) & 3) * 4 + ((2 * tig + 1) >> 2) * 2;
        #pragma unroll
        for (int nb = 0; nb < 8; nb++) {
            float p00 = exp2f(s[nb][0] - mn0);
            float p01 = exp2f(s[nb][1] - mn0);
            float p10 = exp2f(s[nb][2] - mn1);
            float p11 = exp2f(s[nb][3] - mn1);
            rs0 += p00 + p01;
            rs1 += p10 + p11;
            // S col-block nb == PV k-block; write P in PV A-fragment layout
            *(float2*)&pw[nb * 128 + off0] = make_float2(to_tf32(p00), to_tf32(p10));
            *(float2*)&pw[nb * 128 + off1] = make_float2(to_tf32(p01), to_tf32(p11));
        }
        rs0 += __shfl_xor_sync(0xffffffffu, rs0, 1);
        rs0 += __shfl_xor_sync(0xffffffffu, rs0, 2);
        rs1 += __shfl_xor_sync(0xffffffffu, rs1, 1);
        rs1 += __shfl_xor_sync(0xffffffffu, rs1, 2);
        lr[0] = lr[0] * al0 + rs0;
        lr[1] = lr[1] * al1 + rs1;

        // rescale O
        #pragma unroll
        for (int nb = 0; nb < 4; nb++) {
            o[nb][0] *= al0; o[nb][1] *= al0;
            o[nb][2] *= al1; o[nb][3] *= al1;
        }
        __syncwarp();   // Pf is per-warp: order STS before cross-lane LDS

        // ---- O += P V : 64 keys = 8 k-steps ----
        #pragma unroll
        for (int ks2 = 0; ks2 < 8; ks2++) {
            uint32_t a[4];
            const uint4 av = *(const uint4*)&Pf[wid * 1024 + ks2 * 128 + lane * 4];
            a[0] = av.x; a[1] = av.y; a[2] = av.z; a[3] = av.w;
            #pragma unroll
            for (int nb = 0; nb < 4; nb++) {
                uint32_t bfr[2];
                const uint2 bv = *(const uint2*)&Vf[ks2 * 256 + nb * 64 + lane * 2];
                bfr[0] = bv.x; bfr[1] = bv.y;
                mma_tf32(o[nb], a, bfr);
            }
        }
    }

    // ---- normalize + store [b, n, h*32+d] ----
    {
        float inv0 = 1.f / lr[0];
        float inv1 = 1.f / lr[1];
        int row0 = q0 + wid * 16 + grp;
        int row1 = row0 + 8;
        #pragma unroll
        for (int nb = 0; nb < 4; nb++) {
            int col = h * HDIM + nb * 8 + 2 * tig;
            if (row0 < N_TOK)
                *(float2*)&g_att[((size_t)b * N_TOK + row0) * CDIM + col] =
                    make_float2(o[nb][0] * inv0, o[nb][1] * inv0);
            if (row1 < N_TOK)
                *(float2*)&g_att[((size_t)b * N_TOK + row1) * CDIM + col] =
                    make_float2(o[nb][2] * inv1, o[nb][3] * inv1);
        }
    }
}

// ---------------- launch ----------------------------------------------------
extern "C" void kernel_launch(void* const* d_in, const int* in_sizes, int n_in,
                              void* d_out, int out_size) {
    (void)in_sizes; (void)n_in; (void)out_size;
    const float* x        = (const float*)d_in[0];
    const float* mask     = (const float*)d_in[1];
    const float* qkv_w    = (const float*)d_in[2];
    const float* proj_w   = (const float*)d_in[3];
    const float* proj_b   = (const float*)d_in[4];
    const float* bias_tab = (const float*)d_in[5];
    const int*   rel_idx  = (const int*)d_in[6];
    float* out = (float*)d_out;

    cudaFuncSetAttribute(attn_mma,
                         cudaFuncAttributeMaxDynamicSharedMemorySize,
                         ATT_SM_FLOATS * 4);
    cudaFuncSetAttribute(gemm_tc<0>,
                         cudaFuncAttributeMaxDynamicSharedMemorySize,
                         SM_GEMM_FLOATS * 4);
    cudaFuncSetAttribute(gemm_tc<1>,
                         cudaFuncAttributeMaxDynamicSharedMemorySize,
                         SM_GEMM_FLOATS * 4);

    bm_precompute<<<dim3(18, HEADS, 64), 256>>>(bias_tab, rel_idx, mask);
    gemm_tc<0><<<dim3(ODIM / 192, MROWS / 128), 256, SM_GEMM_FLOATS * 4>>>(
        x, qkv_w, nullptr, nullptr, ODIM);
    attn_mma<<<dim3(3, HEADS, BATCH), 256, ATT_SM_FLOATS * 4>>>();
    gemm_tc<1><<<dim3(CDIM / 192, MROWS / 128), 256, SM_GEMM_FLOATS * 4>>>(
        nullptr, proj_w, proj_b, out, CDIM);
}